// round 15
// baseline (speedup 1.0000x reference)
#include <cuda_runtime.h>
#include <cstdint>

// Problem constants (fixed by the reference)
#define NN      2048
#define DF      512
#define MSUP    512
#define TARGET  1536          // N - NUM_SUPER merges
#define MAXDEG  512
#define NSTR    1024          // per-node adjacency capacity (pos-degree ~390 avg)
#define INF64   0xFFFFFFFFFFFFFFFFULL

// Output layout: X_coarse [512,512] | A_coarse [512,512] | P [2048,512]
#define XC_OFF  0
#define AC_OFF  262144
#define P_OFF   524288
#define OUT_N   1572864

// -------- scratch (device globals; no allocation allowed) --------
__device__ int                g_adj[NN * MAXDEG];   // 4 MB (A adjacency)
__device__ int                g_deg[NN];
__device__ int                g_inter[NN * NN];     // 16 MB (upper triangle)
__device__ __align__(16) unsigned long long g_nadj[NN * NSTR];  // 16 MB per-node weights
__device__ int                g_ncnt[NN];
__device__ unsigned long long g_tlist[4096];        // MSF edges (<= 2047)
__device__ int                g_tn;
__device__ int                g_rminfb[NN];
__device__ int                g_labels[NN];
__device__ float              g_wnode[NN];
__device__ float              g_wc[MSUP];
__device__ int                g_mstart[MSUP + 1];
__device__ int                g_mrows[NN];

// ==================== 1) init + adjacency (fused) ====================
__global__ __launch_bounds__(1024)
void k_init(const float* __restrict__ A, float* __restrict__ out) {
    int tid = threadIdx.x;
    int gtid = blockIdx.x * 1024 + tid;
    int nall = gridDim.x * 1024;
    int4 z4 = make_int4(0, 0, 0, 0);
    float4 f4 = make_float4(0.f, 0.f, 0.f, 0.f);
    for (int i = gtid; i < NN * NN / 4; i += nall)
        reinterpret_cast<int4*>(g_inter)[i] = z4;
    for (int i = gtid; i < OUT_N / 4; i += nall)
        reinterpret_cast<float4*>(out)[i] = f4;
    for (int i = gtid; i < NN; i += nall) g_ncnt[i] = 0;
    if (gtid == 0) g_tn = 0;

    int lane = tid & 31, gw = gtid >> 5, nw = nall >> 5;
    for (int row = gw; row < NN; row += nw) {
        const float* rowp = A + (size_t)row * NN;
        int cnt = 0;
        for (int k = 0; k < NN; k += 32) {
            float v = rowp[k + lane];
            unsigned b = __ballot_sync(0xFFFFFFFFu, v > 0.0f);
            if (v > 0.0f) {
                int pos = cnt + __popc(b & ((1u << lane) - 1u));
                if (pos < MAXDEG) g_adj[row * MAXDEG + pos] = k + lane;
            }
            cnt += __popc(b);
        }
        if (lane == 0) g_deg[row] = cnt;
    }
}

// ==================== 2) triangle counting ====================
__global__ void k_tri() {
    int warp = (blockIdx.x * blockDim.x + threadIdx.x) >> 5;
    int lane = threadIdx.x & 31;
    if (warp >= NN) return;
    int d = min(g_deg[warp], MAXDEG);
    const int* nb = &g_adj[warp * MAXDEG];
    if (d <= 32) {
        int mynb = (lane < d) ? nb[lane] : 0;
        for (int a = 0; a < d - 1; a++) {
            int i = __shfl_sync(0xFFFFFFFFu, mynb, a);
            if (lane > a && lane < d)
                atomicAdd(&g_inter[i * NN + mynb], 1);
        }
    } else {
        for (int a = 0; a < d - 1; a++) {
            int i = nb[a];                  // ascending list => i < j below
            int* irow = &g_inter[i * NN];
            for (int b = a + 1 + lane; b < d; b += 32)
                atomicAdd(&irow[nb[b]], 1);
        }
    }
}

// ==================== 3) pair weights -> per-node adjacency lists ====================
// weight ascending == (jaccard descending, then pair index ascending):
//   weight = (~float_bits(jac) << 22) | (i*2048 + j), all distinct.
__global__ __launch_bounds__(256)
void k_pairs() {
    int row = blockIdx.x;                    // grid = NN-1
    int di = g_deg[row];
    const int* irow = &g_inter[row * NN];
    for (int j = row + 1 + threadIdx.x; j < NN; j += 256) {
        int inter = irow[j];
        if (inter > 0) {
            int uni = di + g_deg[j] - inter;          // > 0 when inter > 0
            float jac = __fdiv_rn((float)inter, (float)uni);   // bit-exact vs ref
            unsigned fb = __float_as_uint(jac);
            unsigned long long w =
                ((unsigned long long)(~fb) << 22) | (unsigned)(row * NN + j);
            int si = atomicAdd(&g_ncnt[row], 1);
            if (si < NSTR) g_nadj[row * NSTR + si] = w;
            int sj = atomicAdd(&g_ncnt[j], 1);
            if (sj < NSTR) g_nadj[j * NSTR + sj] = w;
        }
    }
}

// ==================== 4) sort each node's list by weight (block per node) ====================
__global__ __launch_bounds__(256)
void k_sort() {
    __shared__ unsigned long long s[NSTR];   // 8 KB
    int n = blockIdx.x;
    int tid = threadIdx.x;
    int cnt = min(g_ncnt[n], NSTR);
    if (cnt <= 1) return;
    int n2 = 32; while (n2 < cnt) n2 <<= 1;
    unsigned long long* src = &g_nadj[n * NSTR];
    for (int t = tid; t < n2; t += 256) s[t] = (t < cnt) ? src[t] : INF64;
    __syncthreads();
    for (int k = 2; k <= n2; k <<= 1)
        for (int j = k >> 1; j > 0; j >>= 1) {
            for (int t = tid; t < n2; t += 256) {
                int x = t ^ j;
                if (x > t) {
                    unsigned long long a = s[t], b = s[x];
                    if (((t & k) == 0) ? (a > b) : (a < b)) { s[t] = b; s[x] = a; }
                }
            }
            __syncthreads();
        }
    for (int t = tid; t < cnt; t += 256) src[t] = s[t];
}

// ==================== 5) Boruvka (cursor sweeps) + finish, ONE block ====================
__device__ __forceinline__ int ser_find(int* p, int x) {
    while (p[x] != x) { p[x] = p[p[x]]; x = p[x]; }
    return x;
}

__global__ __launch_bounds__(1024, 1)
void k_bor() {
    __shared__ unsigned long long smine[NN];   // 16 KB (finish: tl)
    __shared__ int slab[NN];                   //  8 KB (finish: lab2)
    __shared__ int snew[NN];                   //  8 KB (finish: mlist/ssz/swc/cur)
    __shared__ int scur[NN];                   //  8 KB cursors
    __shared__ int s_h, s_tn, s_cnt;
    int tid = threadIdx.x;

    for (int t = tid; t < NN; t += 1024) {
        slab[t] = t; smine[t] = INF64; scur[t] = 0;
    }
    if (tid == 0) s_tn = 0;
    __syncthreads();

    // ---- Boruvka rounds ----
    for (int round = 0; round < 15; round++) {
        // sweep: per node, first cross edge at/after cursor (sorted by weight)
        for (int n = tid; n < NN; n += 1024) {
            int r = slab[n];
            int c = scur[n];
            int cnt = min(g_ncnt[n], NSTR);
            const unsigned long long* lst = &g_nadj[n * NSTR];
            while (c < cnt) {
                unsigned long long w = lst[c];
                unsigned idx = (unsigned)(w & 0x3FFFFFu);
                int u = idx >> 11, v = idx & (NN - 1);
                int other = (u == n) ? v : u;
                if (slab[other] == r) { c++; continue; }   // intra: skip forever
                atomicMin(&smine[r], w);                   // min cross candidate
                break;                                     // keep cursor ON it
            }
            scur[n] = c;
        }
        __syncthreads();

        // hook (mutual-pair tie-break; distinct weights => same-edge check)
        if (tid == 0) s_h = 0;
        for (int t = tid; t < NN; t += 1024) snew[t] = -1;
        __syncthreads();
        for (int r = tid; r < NN; r += 1024) {
            if (slab[r] == r) {
                unsigned long long w = smine[r];
                if (w != INF64) {
                    unsigned idx = (unsigned)(w & 0x3FFFFFu);
                    int u = idx >> 11, v = idx & (NN - 1);
                    int ru = slab[u], rv = slab[v];
                    int o = (ru == r) ? rv : ru;
                    bool mutual = (smine[o] == w);
                    if (!mutual || r > o) { snew[r] = o; atomicAdd(&s_h, 1); }
                    if (!mutual || r < o) {          // append tree edge once
                        int p = atomicAdd(&s_tn, 1);
                        if (p < 4096) g_tlist[p] = w;
                    }
                }
            }
        }
        __syncthreads();
        for (int r = tid; r < NN; r += 1024) {
            if (snew[r] >= 0) slab[r] = snew[r];
            smine[r] = INF64;
        }
        __syncthreads();
        for (int it = 0; it < 11; it++) {       // full pointer-jump compression
            for (int t = tid; t < NN; t += 1024) snew[t] = slab[slab[t]];
            __syncthreads();
            for (int t = tid; t < NN; t += 1024) slab[t] = snew[t];
            __syncthreads();
        }
        if (s_h == 0) break;                    // MSF complete (stable post-sync)
    }
    if (tid == 0) g_tn = s_tn;
    __syncthreads();

    // ---- finish phase (overlay: tl=smine, lab2=slab, small arrays in snew) ----
    unsigned long long* tl = smine;
    int*   lab2  = slab;
    int*   mlist = snew;                 // 512 ints
    int*   ssz   = snew + 512;           // 512 ints
    float* swc   = (float*)(snew + 1024);// 512 floats
    int*   cur   = snew + 1536;          // 512 ints
    int T = min(g_tn, 2047);

    for (int t = tid; t < 2048; t += 1024) tl[t] = (t < T) ? g_tlist[t] : INF64;
    for (int t = tid; t < NN; t += 1024) lab2[t] = t;
    for (int t = tid; t < MSUP; t += 1024) { ssz[t] = 0; mlist[t] = 0x7FFFFFFF; }
    if (tid == 0) s_cnt = 0;
    __syncthreads();

    // bitonic sort 2048 tree edges ascending by weight
    for (int k = 2; k <= 2048; k <<= 1)
        for (int j = k >> 1; j > 0; j >>= 1) {
            for (int t = tid; t < 2048; t += 1024) {
                int x = t ^ j;
                if (x > t) {
                    unsigned long long a = tl[t], b = tl[x];
                    if (((t & k) == 0) ? (a > b) : (a < b)) { tl[t] = b; tl[x] = a; }
                }
            }
            __syncthreads();
        }

    if (T >= TARGET) {
        // partition = CC of the first TARGET Kruskal-accepted edges
        for (int round = 0; round < 22; round++) {
            for (int e = tid; e < TARGET; e += 1024) {
                unsigned idx = (unsigned)(tl[e] & 0x3FFFFFu);
                int u = idx >> 11, v = idx & (NN - 1);
                int a = lab2[u], b = lab2[v];
                int m = min(a, b);
                if (a != m) atomicMin(&lab2[u], m);
                if (b != m) atomicMin(&lab2[v], m);
            }
            __syncthreads();
            for (int t = tid; t < NN; t += 1024) lab2[t] = lab2[lab2[t]];
            __syncthreads();
        }
    } else {
        // fallback (never expected): serial Kruskal tail incl. zero-jaccard pairs
        if (tid == 0) {
            int merged = 0;
            for (int e = 0; e < T && merged < TARGET; e++) {
                unsigned idx = (unsigned)(tl[e] & 0x3FFFFFu);
                int u = idx >> 11, v = idx & (NN - 1);
                int ru = ser_find(lab2, u), rv = ser_find(lab2, v);
                if (ru != rv) { lab2[rv] = ru; merged++; }
            }
            for (int i = 0; i < NN - 1 && merged < TARGET; i++)
                for (int j = i + 1; j < NN && merged < TARGET; j++)
                    if (g_inter[i * NN + j] == 0) {
                        int ri = ser_find(lab2, i), rj = ser_find(lab2, j);
                        if (ri != rj) { lab2[rj] = ri; merged++; }
                    }
            for (int v = 0; v < NN; v++) g_rminfb[v] = NN;
            for (int v = 0; v < NN; v++) {
                int r = ser_find(lab2, v);
                if (v < g_rminfb[r]) g_rminfb[r] = v;
            }
            for (int v = 0; v < NN; v++) g_labels[v] = g_rminfb[ser_find(lab2, v)];
        }
        __syncthreads();
        for (int t = tid; t < NN; t += 1024) lab2[t] = g_labels[t];
        __syncthreads();
    }

    // component minima -> sorted -> rank == first-occurrence label
    for (int v = tid; v < NN; v += 1024)
        if (lab2[v] == v) mlist[atomicAdd(&s_cnt, 1)] = v;
    __syncthreads();
    for (int k = 2; k <= MSUP; k <<= 1)
        for (int j = k >> 1; j > 0; j >>= 1) {
            for (int t = tid; t < MSUP; t += 1024) {
                int x = t ^ j;
                if (x > t) {
                    int a = mlist[t], b = mlist[x];
                    if (((t & k) == 0) ? (a > b) : (a < b)) { mlist[t] = b; mlist[x] = a; }
                }
            }
            __syncthreads();
        }
    for (int v = tid; v < NN; v += 1024) {
        int m = lab2[v];
        int lo = 0, hi = MSUP - 1;
        while (lo < hi) { int mid = (lo + hi) >> 1; if (mlist[mid] < m) lo = mid + 1; else hi = mid; }
        g_labels[v] = lo;
        atomicAdd(&ssz[lo], 1);
    }
    __syncthreads();
    for (int t = tid; t < MSUP; t += 1024)
        swc[t] = 1.0f / sqrtf((float)ssz[t] + 1e-10f);
    __syncthreads();
    for (int v = tid; v < NN; v += 1024)
        g_wnode[v] = swc[g_labels[v]];

    // member CSR (for X_coarse gather): inclusive scan of ssz (reuse mlist)
    if (tid < MSUP) mlist[tid] = ssz[tid];
    __syncthreads();
    for (int d = 1; d < MSUP; d <<= 1) {
        int v = 0;
        if (tid < MSUP && tid >= d) v = mlist[tid - d];
        __syncthreads();
        if (tid < MSUP) mlist[tid] += v;
        __syncthreads();
    }
    if (tid < MSUP) {
        int excl = mlist[tid] - ssz[tid];
        g_mstart[tid] = excl;
        cur[tid] = excl;
        g_wc[tid] = swc[tid];
    }
    if (tid == 0) g_mstart[MSUP] = NN;
    __syncthreads();
    for (int v = tid; v < NN; v += 1024) {
        int p = atomicAdd(&cur[g_labels[v]], 1);
        g_mrows[p] = v;
    }
}

// ==================== 6) fused epilogue ====================
__global__ __launch_bounds__(1024)
void k_epi(const float* __restrict__ X, float* __restrict__ out) {
    __shared__ int slabels[NN];
    __shared__ float swn[NN];
    int tid = threadIdx.x;
    int gtid = blockIdx.x * 1024 + tid;
    int nall = gridDim.x * 1024;
    for (int t = tid; t < NN; t += 1024) {
        slabels[t] = g_labels[t];
        swn[t] = g_wnode[t];
    }
    __syncthreads();
    // P
    for (int i = gtid; i < NN; i += nall)
        out[P_OFF + i * MSUP + slabels[i]] = swn[i];
    // X_coarse = P^T X : deterministic member-CSR gather, coalesced in d
    for (int idx = gtid; idx < MSUP * DF; idx += nall) {
        int s = idx >> 9, d = idx & (DF - 1);
        int b = g_mstart[s], e = g_mstart[s + 1];
        float acc = 0.0f;
        for (int m = b; m < e; m++)
            acc += X[g_mrows[m] * DF + d];
        out[XC_OFF + idx] = g_wc[s] * acc;
    }
    // A_coarse = P^T A P : A is binary by construction => edge value 1.0
    int lane = tid & 31, gw = gtid >> 5, nw = nall >> 5;
    for (int node = gw; node < NN; node += nw) {
        int d = min(g_deg[node], MAXDEG);
        float wi = swn[node];
        int li = slabels[node];
        for (int a = lane; a < d; a += 32) {
            int j = g_adj[node * MAXDEG + a];
            atomicAdd(&out[AC_OFF + li * MSUP + slabels[j]], wi * swn[j]);
        }
    }
}

// -------- launch --------
extern "C" void kernel_launch(void* const* d_in, const int* in_sizes, int n_in,
                              void* d_out, int out_size) {
    const float* X = (const float*)d_in[0];
    const float* A = (const float*)d_in[1];
    float* out = (float*)d_out;

    k_init<<<148, 1024>>>(A, out);
    k_tri<<<256, 256>>>();
    k_pairs<<<NN - 1, 256>>>();
    k_sort<<<NN, 256>>>();
    k_bor<<<1, 1024>>>();
    k_epi<<<148, 1024>>>(X, out);
}

// round 16
// speedup vs baseline: 2.6221x; 2.6221x over previous
#include <cuda_runtime.h>
#include <cstdint>

// Problem constants (fixed by the reference)
#define NN      2048
#define DF      512
#define MSUP    512
#define TARGET  1536          // N - NUM_SUPER merges
#define MAXDEG  512
#define MAXE    (1 << 21)
#define INF64   0xFFFFFFFFFFFFFFFFULL

// Output layout: X_coarse [512,512] | A_coarse [512,512] | P [2048,512]
#define XC_OFF  0
#define AC_OFF  262144
#define P_OFF   524288
#define OUT_N   1572864

// -------- scratch (device globals; no allocation allowed) --------
__device__ int                g_adj[NN * MAXDEG];   // 4 MB
__device__ int                g_deg[NN];
__device__ int                g_inter[NN * NN];     // 16 MB (upper triangle)
__device__ __align__(16) unsigned long long g_edges[MAXE];    // buffer 0
__device__ __align__(16) unsigned long long g_edges2[MAXE];   // buffer 1
__device__ int                g_ne;
__device__ int                g_nelive;             // live edges for next round
__device__ int                g_necnt;              // compaction cursor
__device__ unsigned long long g_mine[NN];           // per-root min outgoing edge
__device__ int                g_lab[NN];
__device__ unsigned long long g_tlist[4096];        // MSF edges (<= 2047)
__device__ int                g_tn;
__device__ int                g_active;
__device__ unsigned           g_done_e = 0;
__device__ unsigned           g_done_r = 0;
__device__ int                g_rminfb[NN];
__device__ int                g_labels[NN];
__device__ float              g_wnode[NN];
__device__ float              g_wc[MSUP];
__device__ int                g_mstart[MSUP + 1];
__device__ int                g_mrows[NN];

// -------- Boruvka hook (one block; slab holds current labels) --------
template <int NT>
__device__ void do_hook(int* slab, int* snew, int tid) {
    __shared__ int s_h, s_chg;
    if (tid == 0) s_h = 0;
    for (int t = tid; t < NN; t += NT) snew[t] = -1;
    __syncthreads();
    for (int r = tid; r < NN; r += NT) {
        if (slab[r] == r) {
            unsigned long long w = g_mine[r];
            if (w != INF64) {
                unsigned idx = (unsigned)(w & 0x3FFFFFu);
                int u = idx >> 11, v = idx & (NN - 1);
                int ru = slab[u], rv = slab[v];
                int o = (ru == r) ? rv : ru;
                bool mutual = (g_mine[o] == w);     // distinct weights => same edge
                if (!mutual || r > o) { snew[r] = o; atomicAdd(&s_h, 1); }
                if (!mutual || r < o) {             // append tree edge exactly once
                    int p = atomicAdd(&g_tn, 1);
                    if (p < 4096) g_tlist[p] = w;
                }
            }
        }
    }
    __syncthreads();
    for (int r = tid; r < NN; r += NT) {
        if (snew[r] >= 0) slab[r] = snew[r];
        g_mine[r] = INF64;
    }
    __syncthreads();
    // pointer jumping with convergence early-exit (identical fixpoint)
    for (int it = 0; it < 11; it++) {
        if (tid == 0) s_chg = 0;
        __syncthreads();
        bool chg = false;
        for (int t = tid; t < NN; t += NT) {
            int nv = slab[slab[t]];
            snew[t] = nv;
            chg |= (nv != slab[t]);
        }
        if (chg) s_chg = 1;
        __syncthreads();
        for (int t = tid; t < NN; t += NT) slab[t] = snew[t];
        __syncthreads();
        if (!s_chg) break;
    }
    for (int t = tid; t < NN; t += NT) g_lab[t] = slab[t];
    if (tid == 0) g_active = s_h;                   // 0 => MSF complete
}

// ==================== 1) init + adjacency (fused) ====================
__global__ __launch_bounds__(1024)
void k_init(const float* __restrict__ A, float* __restrict__ out) {
    int tid = threadIdx.x;
    int gtid = blockIdx.x * 1024 + tid;
    int nall = gridDim.x * 1024;
    int4 z4 = make_int4(0, 0, 0, 0);
    float4 f4 = make_float4(0.f, 0.f, 0.f, 0.f);
    for (int i = gtid; i < NN * NN / 4; i += nall)
        reinterpret_cast<int4*>(g_inter)[i] = z4;
    for (int i = gtid; i < OUT_N / 4; i += nall)
        reinterpret_cast<float4*>(out)[i] = f4;
    for (int i = gtid; i < NN; i += nall) { g_mine[i] = INF64; g_lab[i] = i; }
    if (gtid == 0) {
        g_ne = 0; g_tn = 0; g_active = 1;
        g_done_e = 0; g_done_r = 0; g_necnt = 0;
    }

    int lane = tid & 31, gw = gtid >> 5, nw = nall >> 5;
    for (int row = gw; row < NN; row += nw) {
        const float* rowp = A + (size_t)row * NN;
        int cnt = 0;
        for (int k = 0; k < NN; k += 32) {
            float v = rowp[k + lane];
            unsigned b = __ballot_sync(0xFFFFFFFFu, v > 0.0f);
            if (v > 0.0f) {
                int pos = cnt + __popc(b & ((1u << lane) - 1u));
                if (pos < MAXDEG) g_adj[row * MAXDEG + pos] = k + lane;
            }
            cnt += __popc(b);
        }
        if (lane == 0) g_deg[row] = cnt;
    }
}

// ==================== 2) triangle counting ====================
__global__ void k_tri() {
    int warp = (blockIdx.x * blockDim.x + threadIdx.x) >> 5;
    int lane = threadIdx.x & 31;
    if (warp >= NN) return;
    int d = min(g_deg[warp], MAXDEG);
    const int* nb = &g_adj[warp * MAXDEG];
    if (d <= 32) {
        int mynb = (lane < d) ? nb[lane] : 0;
        for (int a = 0; a < d - 1; a++) {
            int i = __shfl_sync(0xFFFFFFFFu, mynb, a);
            if (lane > a && lane < d)
                atomicAdd(&g_inter[i * NN + mynb], 1);
        }
    } else {
        for (int a = 0; a < d - 1; a++) {
            int i = nb[a];                  // ascending list => i < j below
            int* irow = &g_inter[i * NN];
            for (int b = a + 1 + lane; b < d; b += 32)
                atomicAdd(&irow[nb[b]], 1);
        }
    }
}

// ==================== 3) edges + sweep #1 + inline hook #1 ====================
// weight ascending == (jaccard descending, then pair index ascending):
//   weight = (~float_bits(jac) << 22) | (i*2048 + j), 54 bits, all distinct.
__global__ __launch_bounds__(512)
void k_edges() {
    __shared__ __align__(16) unsigned long long sbuf[NN];   // 16 KB
    __shared__ unsigned long long sred[512];
    __shared__ int scnt, sbase, s_last;
    int tid = threadIdx.x, lane = tid & 31;
    int row = blockIdx.x;                    // grid = NN-1
    if (tid == 0) { scnt = 0; s_last = 0; }
    __syncthreads();

    int di = g_deg[row];
    const int* irow = &g_inter[row * NN];
    unsigned long long wmin = INF64;
    for (int jb = row + 1; jb < NN; jb += 512) {
        int j = jb + tid;
        bool pos = (j < NN) && (irow[j] > 0);
        unsigned b = __ballot_sync(0xFFFFFFFFu, pos);
        int nwp = __popc(b);
        int wbase = 0;
        if (nwp) {
            if (lane == 0) wbase = atomicAdd(&scnt, nwp);
            wbase = __shfl_sync(0xFFFFFFFFu, wbase, 0);
        }
        if (pos) {
            int inter = irow[j];
            int uni = di + g_deg[j] - inter;          // > 0 when inter > 0
            float jac = __fdiv_rn((float)inter, (float)uni);   // bit-exact vs ref
            unsigned fb = __float_as_uint(jac);
            unsigned long long w =
                ((unsigned long long)(~fb) << 22) | (unsigned)(row * NN + j);
            sbuf[wbase + __popc(b & ((1u << lane) - 1u))] = w;
            wmin = min(wmin, w);
            if (g_mine[j] > w) atomicMin(&g_mine[j], w);   // filtered sweep #1
        }
    }
    sred[tid] = wmin;
    __syncthreads();
    for (int d = 256; d > 0; d >>= 1) {
        if (tid < d) sred[tid] = min(sred[tid], sred[tid + d]);
        __syncthreads();
    }
    if (tid == 0) {
        if (sred[0] != INF64 && g_mine[row] > sred[0]) atomicMin(&g_mine[row], sred[0]);
        sbase = atomicAdd(&g_ne, scnt);               // one global atomic/row
    }
    __syncthreads();
    for (int t = tid; t < scnt; t += 512)
        if (sbase + t < MAXE) g_edges[sbase + t] = sbuf[t];

    // ---- last-block-done: the final block performs hook #1 inline ----
    __threadfence();
    __syncthreads();
    if (tid == 0 && atomicAdd(&g_done_e, 1u) == gridDim.x - 1) {
        s_last = 1; g_done_e = 0;
    }
    __syncthreads();
    if (s_last) {
        __threadfence();
        int* slab = (int*)sbuf;                       // reuse smem
        int* snew = (int*)(sbuf + 1024);
        for (int t = tid; t < NN; t += 512) slab[t] = t;   // labels = identity
        __syncthreads();
        if (tid == 0) g_nelive = min(g_ne, MAXE);
        do_hook<512>(slab, snew, tid);
    }
}

// ==================== 4) Boruvka round (1024 thr): sweep + compaction + hook ====================
__global__ __launch_bounds__(1024)
void k_round(int parity) {
    if (g_active == 0) return;
    __shared__ unsigned long long smine[NN];          // 16 KB per-root block min
    __shared__ int slab[NN];                          //  8 KB
    __shared__ __align__(16) unsigned long long stg[1024];  // 8 KB staging
    __shared__ int troot[NN];                         //  8 KB touched roots
    __shared__ int s_last, scnt, sflush, s_nroot;
    int tid = threadIdx.x, lane = tid & 31;
    for (int t = tid; t < NN; t += 1024) { slab[t] = g_lab[t]; smine[t] = INF64; }
    if (tid == 0) { s_last = 0; scnt = 0; s_nroot = 0; }
    __syncthreads();

    const unsigned long long* esrc = parity ? g_edges2 : g_edges;
    unsigned long long*       edst = parity ? g_edges  : g_edges2;
    int ne = g_nelive;
    int per = (ne + gridDim.x - 1) / gridDim.x;
    int b0 = blockIdx.x * per;
    int b1 = min(b0 + per, ne);

    for (int base = b0; base < b1; base += 1024) {
        int e = base + tid;
        bool cross = false;
        unsigned long long w = 0;
        if (e < b1) {
            w = esrc[e];
            unsigned idx = (unsigned)(w & 0x3FFFFFu);
            int u = idx >> 11, v = idx & (NN - 1);
            int ru = slab[u], rv = slab[v];
            if (ru != rv) {
                cross = true;
                // first-touch tracking: atomicMin returns old value
                if (atomicMin(&smine[ru], w) == INF64) troot[atomicAdd(&s_nroot, 1)] = ru;
                if (atomicMin(&smine[rv], w) == INF64) troot[atomicAdd(&s_nroot, 1)] = rv;
            }
        }
        // warp-aggregated staging append
        unsigned b = __ballot_sync(0xFFFFFFFFu, cross);
        int nwp = __popc(b);
        int wb = 0;
        if (nwp) {
            if (lane == 0) wb = atomicAdd(&scnt, nwp);
            wb = __shfl_sync(0xFFFFFFFFu, wb, 0);
        }
        if (cross) stg[wb + __popc(b & ((1u << lane) - 1u))] = w;
        __syncthreads();
        // per-chunk flush (stg capacity == chunk size)
        if (scnt > 0) {
            if (tid == 0) sflush = atomicAdd(&g_necnt, scnt);
            __syncthreads();
            for (int t = tid; t < scnt; t += 1024) edst[sflush + t] = stg[t];
            __syncthreads();
            if (tid == 0) scnt = 0;
        }
        __syncthreads();
    }
    // flush only TOUCHED block minima (read-check kills L2 serialization)
    for (int t = tid; t < s_nroot; t += 1024) {
        int r = troot[t];
        unsigned long long w = smine[r];
        if (g_mine[r] > w) atomicMin(&g_mine[r], w);
    }

    __threadfence();
    __syncthreads();
    if (tid == 0 && atomicAdd(&g_done_r, 1u) == gridDim.x - 1) {
        s_last = 1; g_done_r = 0;
    }
    __syncthreads();
    if (s_last) {
        __threadfence();
        if (tid == 0) { g_nelive = min(g_necnt, MAXE); g_necnt = 0; }
        int* snew = (int*)stg;                        // staging free now (2048 ints)
        do_hook<1024>(slab, snew, tid);               // slab already current
    }
}

// ==================== 5) finish (single block) ====================
__device__ __forceinline__ int ser_find(int* p, int x) {
    while (p[x] != x) { p[x] = p[p[x]]; x = p[x]; }
    return x;
}

__global__ __launch_bounds__(1024, 1)
void k_finish() {
    __shared__ __align__(16) char sm[32768];
    __shared__ int s_cnt, s_chgf;
    unsigned long long* tl = (unsigned long long*)sm;          // 16K
    int*   lab2  = (int*)(sm + 16384);                         //  8K
    int*   mlist = (int*)(sm + 24576);                         //  2K
    int*   ssz   = (int*)(sm + 26624);                         //  2K
    float* swc   = (float*)(sm + 28672);                       //  2K
    int*   cur   = (int*)(sm + 30720);                         //  2K
    int tid = threadIdx.x;
    int T = min(g_tn, 2047);

    for (int t = tid; t < 2048; t += 1024) tl[t] = (t < T) ? g_tlist[t] : INF64;
    for (int t = tid; t < NN; t += 1024) lab2[t] = t;
    for (int t = tid; t < MSUP; t += 1024) { ssz[t] = 0; mlist[t] = 0x7FFFFFFF; }
    if (tid == 0) s_cnt = 0;
    __syncthreads();

    // bitonic sort 2048 tree edges ascending by weight
    for (int k = 2; k <= 2048; k <<= 1)
        for (int j = k >> 1; j > 0; j >>= 1) {
            for (int t = tid; t < 2048; t += 1024) {
                int x = t ^ j;
                if (x > t) {
                    unsigned long long a = tl[t], b = tl[x];
                    if (((t & k) == 0) ? (a > b) : (a < b)) { tl[t] = b; tl[x] = a; }
                }
            }
            __syncthreads();
        }

    if (T >= TARGET) {
        // partition = CC of the first TARGET Kruskal-accepted edges.
        // converged <=> an edge pass performs zero atomicMin (labels stationary
        // => per-component constant => equal to component-min fixpoint).
        for (int round = 0; round < 22; round++) {
            if (tid == 0) s_chgf = 0;
            __syncthreads();
            bool chg = false;
            for (int e = tid; e < TARGET; e += 1024) {
                unsigned idx = (unsigned)(tl[e] & 0x3FFFFFu);
                int u = idx >> 11, v = idx & (NN - 1);
                int a = lab2[u], b = lab2[v];
                int m = min(a, b);
                if (a != m) { atomicMin(&lab2[u], m); chg = true; }
                if (b != m) { atomicMin(&lab2[v], m); chg = true; }
            }
            if (chg) s_chgf = 1;
            __syncthreads();
            for (int t = tid; t < NN; t += 1024) lab2[t] = lab2[lab2[t]];
            __syncthreads();
            if (!s_chgf) break;
        }
    } else {
        // fallback (never expected): serial Kruskal tail incl. zero-jaccard pairs
        if (tid == 0) {
            int merged = 0;
            for (int e = 0; e < T && merged < TARGET; e++) {
                unsigned idx = (unsigned)(tl[e] & 0x3FFFFFu);
                int u = idx >> 11, v = idx & (NN - 1);
                int ru = ser_find(lab2, u), rv = ser_find(lab2, v);
                if (ru != rv) { lab2[rv] = ru; merged++; }
            }
            for (int i = 0; i < NN - 1 && merged < TARGET; i++)
                for (int j = i + 1; j < NN && merged < TARGET; j++)
                    if (g_inter[i * NN + j] == 0) {
                        int ri = ser_find(lab2, i), rj = ser_find(lab2, j);
                        if (ri != rj) { lab2[rj] = ri; merged++; }
                    }
            for (int v = 0; v < NN; v++) g_rminfb[v] = NN;
            for (int v = 0; v < NN; v++) {
                int r = ser_find(lab2, v);
                if (v < g_rminfb[r]) g_rminfb[r] = v;
            }
            for (int v = 0; v < NN; v++) g_labels[v] = g_rminfb[ser_find(lab2, v)];
        }
        __syncthreads();
        for (int t = tid; t < NN; t += 1024) lab2[t] = g_labels[t];
        __syncthreads();
    }

    // component minima -> sorted -> rank == first-occurrence label
    for (int v = tid; v < NN; v += 1024)
        if (lab2[v] == v) mlist[atomicAdd(&s_cnt, 1)] = v;
    __syncthreads();
    for (int k = 2; k <= MSUP; k <<= 1)
        for (int j = k >> 1; j > 0; j >>= 1) {
            for (int t = tid; t < MSUP; t += 1024) {
                int x = t ^ j;
                if (x > t) {
                    int a = mlist[t], b = mlist[x];
                    if (((t & k) == 0) ? (a > b) : (a < b)) { mlist[t] = b; mlist[x] = a; }
                }
            }
            __syncthreads();
        }
    for (int v = tid; v < NN; v += 1024) {
        int m = lab2[v];
        int lo = 0, hi = MSUP - 1;
        while (lo < hi) { int mid = (lo + hi) >> 1; if (mlist[mid] < m) lo = mid + 1; else hi = mid; }
        g_labels[v] = lo;
        atomicAdd(&ssz[lo], 1);
    }
    __syncthreads();
    for (int t = tid; t < MSUP; t += 1024)
        swc[t] = 1.0f / sqrtf((float)ssz[t] + 1e-10f);
    __syncthreads();
    for (int v = tid; v < NN; v += 1024)
        g_wnode[v] = swc[g_labels[v]];

    // member CSR (for X_coarse gather): inclusive scan of ssz (reuse mlist)
    if (tid < MSUP) mlist[tid] = ssz[tid];
    __syncthreads();
    for (int d = 1; d < MSUP; d <<= 1) {
        int v = 0;
        if (tid < MSUP && tid >= d) v = mlist[tid - d];
        __syncthreads();
        if (tid < MSUP) mlist[tid] += v;
        __syncthreads();
    }
    if (tid < MSUP) {
        int excl = mlist[tid] - ssz[tid];
        g_mstart[tid] = excl;
        cur[tid] = excl;
        g_wc[tid] = swc[tid];
    }
    if (tid == 0) g_mstart[MSUP] = NN;
    __syncthreads();
    for (int v = tid; v < NN; v += 1024) {
        int p = atomicAdd(&cur[g_labels[v]], 1);
        g_mrows[p] = v;
    }
}

// ==================== 6) fused epilogue ====================
__global__ __launch_bounds__(1024)
void k_epi(const float* __restrict__ X, float* __restrict__ out) {
    __shared__ int slabels[NN];
    __shared__ float swn[NN];
    int tid = threadIdx.x;
    int gtid = blockIdx.x * 1024 + tid;
    int nall = gridDim.x * 1024;
    for (int t = tid; t < NN; t += 1024) {
        slabels[t] = g_labels[t];
        swn[t] = g_wnode[t];
    }
    __syncthreads();
    // P
    for (int i = gtid; i < NN; i += nall)
        out[P_OFF + i * MSUP + slabels[i]] = swn[i];
    // X_coarse = P^T X : deterministic member-CSR gather, coalesced in d
    for (int idx = gtid; idx < MSUP * DF; idx += nall) {
        int s = idx >> 9, d = idx & (DF - 1);
        int b = g_mstart[s], e = g_mstart[s + 1];
        float acc = 0.0f;
        for (int m = b; m < e; m++)
            acc += X[g_mrows[m] * DF + d];
        out[XC_OFF + idx] = g_wc[s] * acc;
    }
    // A_coarse = P^T A P : A is binary by construction => edge value 1.0
    int lane = tid & 31, gw = gtid >> 5, nw = nall >> 5;
    for (int node = gw; node < NN; node += nw) {
        int d = min(g_deg[node], MAXDEG);
        float wi = swn[node];
        int li = slabels[node];
        for (int a = lane; a < d; a += 32) {
            int j = g_adj[node * MAXDEG + a];
            atomicAdd(&out[AC_OFF + li * MSUP + slabels[j]], wi * swn[j]);
        }
    }
}

// -------- launch --------
extern "C" void kernel_launch(void* const* d_in, const int* in_sizes, int n_in,
                              void* d_out, int out_size) {
    const float* X = (const float*)d_in[0];
    const float* A = (const float*)d_in[1];
    float* out = (float*)d_out;

    k_init<<<148, 1024>>>(A, out);
    k_tri<<<256, 256>>>();
    k_edges<<<NN - 1, 512>>>();          // + filtered sweep#1 + hook#1
    for (int r = 0; r < 10; r++)         // active rounds form a prefix
        k_round<<<148, 1024>>>(r & 1);   // no-op after convergence
    k_finish<<<1, 1024>>>();
    k_epi<<<148, 1024>>>(X, out);
}

// round 17
// speedup vs baseline: 2.7403x; 1.0451x over previous
#include <cuda_runtime.h>
#include <cstdint>

// Problem constants (fixed by the reference)
#define NN      2048
#define DF      512
#define MSUP    512
#define TARGET  1536          // N - NUM_SUPER merges
#define MAXDEG  512
#define MAXE    (1 << 21)
#define INF64   0xFFFFFFFFFFFFFFFFULL

// Output layout: X_coarse [512,512] | A_coarse [512,512] | P [2048,512]
#define XC_OFF  0
#define AC_OFF  262144
#define P_OFF   524288
#define OUT_N   1572864

// -------- scratch (device globals; no allocation allowed) --------
__device__ int                g_adj[NN * MAXDEG];   // 4 MB
__device__ int                g_deg[NN];
__device__ int                g_inter[NN * NN];     // 16 MB (upper triangle)
__device__ __align__(16) unsigned long long g_edges[MAXE];    // static edge list
__device__ int                g_ne;
__device__ unsigned long long g_mine[NN];           // per-root min outgoing edge
__device__ int                g_lab[NN];
__device__ unsigned long long g_tlist[4096];        // MSF edges (<= 2047)
__device__ int                g_tn;
__device__ int                g_active;
__device__ unsigned           g_done_e = 0;
__device__ unsigned           g_done_r = 0;
__device__ int                g_rminfb[NN];
__device__ int                g_labels[NN];
__device__ float              g_wnode[NN];
__device__ float              g_wc[MSUP];
__device__ int                g_mstart[MSUP + 1];
__device__ int                g_mrows[NN];

// -------- Boruvka hook (one block; slab holds current labels) --------
template <int NT>
__device__ void do_hook(int* slab, int* snew, int tid) {
    __shared__ int s_h, s_chg;
    if (tid == 0) s_h = 0;
    for (int t = tid; t < NN; t += NT) snew[t] = -1;
    __syncthreads();
    for (int r = tid; r < NN; r += NT) {
        if (slab[r] == r) {
            unsigned long long w = g_mine[r];
            if (w != INF64) {
                unsigned idx = (unsigned)(w & 0x3FFFFFu);
                int u = idx >> 11, v = idx & (NN - 1);
                int ru = slab[u], rv = slab[v];
                int o = (ru == r) ? rv : ru;
                bool mutual = (g_mine[o] == w);     // distinct weights => same edge
                if (!mutual || r > o) { snew[r] = o; atomicAdd(&s_h, 1); }
                if (!mutual || r < o) {             // append tree edge exactly once
                    int p = atomicAdd(&g_tn, 1);
                    if (p < 4096) g_tlist[p] = w;
                }
            }
        }
    }
    __syncthreads();
    for (int r = tid; r < NN; r += NT) {
        if (snew[r] >= 0) slab[r] = snew[r];
        g_mine[r] = INF64;
    }
    __syncthreads();
    // pointer jumping with convergence early-exit
    for (int it = 0; it < 11; it++) {
        if (tid == 0) s_chg = 0;
        __syncthreads();
        bool chg = false;
        for (int t = tid; t < NN; t += NT) {
            int nv = slab[slab[t]];
            snew[t] = nv;
            chg |= (nv != slab[t]);
        }
        if (chg) s_chg = 1;
        __syncthreads();
        for (int t = tid; t < NN; t += NT) slab[t] = snew[t];
        __syncthreads();
        if (!s_chg) break;
    }
    for (int t = tid; t < NN; t += NT) g_lab[t] = slab[t];
    if (tid == 0) g_active = s_h;                   // 0 => MSF complete
}

// ==================== 1) init + adjacency (fused) ====================
__global__ __launch_bounds__(1024)
void k_init(const float* __restrict__ A, float* __restrict__ out) {
    int tid = threadIdx.x;
    int gtid = blockIdx.x * 1024 + tid;
    int nall = gridDim.x * 1024;
    int4 z4 = make_int4(0, 0, 0, 0);
    float4 f4 = make_float4(0.f, 0.f, 0.f, 0.f);
    for (int i = gtid; i < NN * NN / 4; i += nall)
        reinterpret_cast<int4*>(g_inter)[i] = z4;
    for (int i = gtid; i < OUT_N / 4; i += nall)
        reinterpret_cast<float4*>(out)[i] = f4;
    for (int i = gtid; i < NN; i += nall) { g_mine[i] = INF64; g_lab[i] = i; }
    if (gtid == 0) {
        g_ne = 0; g_tn = 0; g_active = 1;
        g_done_e = 0; g_done_r = 0;
    }

    int lane = tid & 31, gw = gtid >> 5, nw = nall >> 5;
    for (int row = gw; row < NN; row += nw) {
        const float* rowp = A + (size_t)row * NN;
        int cnt = 0;
        for (int k = 0; k < NN; k += 32) {
            float v = rowp[k + lane];
            unsigned b = __ballot_sync(0xFFFFFFFFu, v > 0.0f);
            if (v > 0.0f) {
                int pos = cnt + __popc(b & ((1u << lane) - 1u));
                if (pos < MAXDEG) g_adj[row * MAXDEG + pos] = k + lane;
            }
            cnt += __popc(b);
        }
        if (lane == 0) g_deg[row] = cnt;
    }
}

// ==================== 2) triangle counting ====================
__global__ void k_tri() {
    int warp = (blockIdx.x * blockDim.x + threadIdx.x) >> 5;
    int lane = threadIdx.x & 31;
    if (warp >= NN) return;
    int d = min(g_deg[warp], MAXDEG);
    const int* nb = &g_adj[warp * MAXDEG];
    if (d <= 32) {
        int mynb = (lane < d) ? nb[lane] : 0;
        for (int a = 0; a < d - 1; a++) {
            int i = __shfl_sync(0xFFFFFFFFu, mynb, a);
            if (lane > a && lane < d)
                atomicAdd(&g_inter[i * NN + mynb], 1);
        }
    } else {
        for (int a = 0; a < d - 1; a++) {
            int i = nb[a];                  // ascending list => i < j below
            int* irow = &g_inter[i * NN];
            for (int b = a + 1 + lane; b < d; b += 32)
                atomicAdd(&irow[nb[b]], 1);
        }
    }
}

// ==================== 3) edges + sweep #1 + inline hook #1 ====================
// weight ascending == (jaccard descending, then pair index ascending):
//   weight = (~float_bits(jac) << 22) | (i*2048 + j), 54 bits, all distinct.
__global__ __launch_bounds__(512)
void k_edges() {
    __shared__ __align__(16) unsigned long long sbuf[NN];   // 16 KB
    __shared__ unsigned long long sred[512];
    __shared__ int scnt, sbase, s_last;
    int tid = threadIdx.x, lane = tid & 31;
    int row = blockIdx.x;                    // grid = NN-1
    if (tid == 0) { scnt = 0; s_last = 0; }
    __syncthreads();

    int di = g_deg[row];
    const int* irow = &g_inter[row * NN];
    unsigned long long wmin = INF64;
    for (int jb = row + 1; jb < NN; jb += 512) {
        int j = jb + tid;
        bool pos = (j < NN) && (irow[j] > 0);
        unsigned b = __ballot_sync(0xFFFFFFFFu, pos);
        int nwp = __popc(b);
        int wbase = 0;
        if (nwp) {
            if (lane == 0) wbase = atomicAdd(&scnt, nwp);
            wbase = __shfl_sync(0xFFFFFFFFu, wbase, 0);
        }
        if (pos) {
            int inter = irow[j];
            int uni = di + g_deg[j] - inter;          // > 0 when inter > 0
            float jac = __fdiv_rn((float)inter, (float)uni);   // bit-exact vs ref
            unsigned fb = __float_as_uint(jac);
            unsigned long long w =
                ((unsigned long long)(~fb) << 22) | (unsigned)(row * NN + j);
            sbuf[wbase + __popc(b & ((1u << lane) - 1u))] = w;
            wmin = min(wmin, w);
            if (g_mine[j] > w) atomicMin(&g_mine[j], w);   // filtered sweep #1
        }
    }
    sred[tid] = wmin;
    __syncthreads();
    for (int d = 256; d > 0; d >>= 1) {
        if (tid < d) sred[tid] = min(sred[tid], sred[tid + d]);
        __syncthreads();
    }
    if (tid == 0) {
        if (sred[0] != INF64 && g_mine[row] > sred[0]) atomicMin(&g_mine[row], sred[0]);
        sbase = atomicAdd(&g_ne, scnt);               // one global atomic/row
    }
    __syncthreads();
    for (int t = tid; t < scnt; t += 512)
        if (sbase + t < MAXE) g_edges[sbase + t] = sbuf[t];

    // ---- last-block-done: the final block performs hook #1 inline ----
    __threadfence();
    __syncthreads();
    if (tid == 0 && atomicAdd(&g_done_e, 1u) == gridDim.x - 1) {
        s_last = 1; g_done_e = 0;
    }
    __syncthreads();
    if (s_last) {
        __threadfence();
        int* slab = (int*)sbuf;                       // reuse smem
        int* snew = (int*)(sbuf + 1024);
        for (int t = tid; t < NN; t += 512) slab[t] = t;   // labels = identity
        __syncthreads();
        do_hook<512>(slab, snew, tid);
    }
}

// ==================== 4) Boruvka round: pure sweep (no compaction) + hook ====================
__global__ __launch_bounds__(1024)
void k_round() {
    if (g_active == 0) return;
    __shared__ unsigned long long smine[NN];          // 16 KB per-root block min
    __shared__ int slab[NN];                          //  8 KB
    __shared__ int troot[NN];                         //  8 KB touched roots
    __shared__ int s_last, s_nroot;
    int tid = threadIdx.x;
    for (int t = tid; t < NN; t += 1024) { slab[t] = g_lab[t]; smine[t] = INF64; }
    if (tid == 0) { s_last = 0; s_nroot = 0; }
    __syncthreads();

    // static edge list: L2-resident after round 1; sync-free pipelined scan
    int ne = min(g_ne, MAXE);
    int per = (ne + gridDim.x - 1) / gridDim.x;
    int b0 = blockIdx.x * per;
    int b1 = min(b0 + per, ne);
    for (int e = b0 + tid; e < b1; e += 1024) {
        unsigned long long w = g_edges[e];
        unsigned idx = (unsigned)(w & 0x3FFFFFu);
        int u = idx >> 11, v = idx & (NN - 1);
        int ru = slab[u], rv = slab[v];
        if (ru != rv) {
            // first-touch tracking: atomicMin returns old value
            if (atomicMin(&smine[ru], w) == INF64) troot[atomicAdd(&s_nroot, 1)] = ru;
            if (atomicMin(&smine[rv], w) == INF64) troot[atomicAdd(&s_nroot, 1)] = rv;
        }
    }
    __syncthreads();
    // flush only TOUCHED block minima (read-check kills L2 serialization)
    for (int t = tid; t < s_nroot; t += 1024) {
        int r = troot[t];
        unsigned long long w = smine[r];
        if (g_mine[r] > w) atomicMin(&g_mine[r], w);
    }

    __threadfence();
    __syncthreads();
    if (tid == 0 && atomicAdd(&g_done_r, 1u) == gridDim.x - 1) {
        s_last = 1; g_done_r = 0;
    }
    __syncthreads();
    if (s_last) {
        __threadfence();
        int* snew = troot;                            // free now (2048 ints)
        do_hook<1024>(slab, snew, tid);               // slab already current
    }
}

// ==================== 5) finish (single block) ====================
__device__ __forceinline__ int ser_find(int* p, int x) {
    while (p[x] != x) { p[x] = p[p[x]]; x = p[x]; }
    return x;
}

__global__ __launch_bounds__(1024, 1)
void k_finish() {
    __shared__ __align__(16) char sm[32768];
    __shared__ int s_cnt, s_chgf;
    unsigned long long* tl = (unsigned long long*)sm;          // 16K
    int*   lab2  = (int*)(sm + 16384);                         //  8K
    int*   mlist = (int*)(sm + 24576);                         //  2K
    int*   ssz   = (int*)(sm + 26624);                         //  2K
    float* swc   = (float*)(sm + 28672);                       //  2K
    int*   cur   = (int*)(sm + 30720);                         //  2K
    int tid = threadIdx.x;
    int T = min(g_tn, 2047);

    for (int t = tid; t < 2048; t += 1024) tl[t] = (t < T) ? g_tlist[t] : INF64;
    for (int t = tid; t < NN; t += 1024) lab2[t] = t;
    for (int t = tid; t < MSUP; t += 1024) { ssz[t] = 0; mlist[t] = 0x7FFFFFFF; }
    if (tid == 0) s_cnt = 0;
    __syncthreads();

    // bitonic sort 2048 tree edges ascending by weight
    for (int k = 2; k <= 2048; k <<= 1)
        for (int j = k >> 1; j > 0; j >>= 1) {
            for (int t = tid; t < 2048; t += 1024) {
                int x = t ^ j;
                if (x > t) {
                    unsigned long long a = tl[t], b = tl[x];
                    if (((t & k) == 0) ? (a > b) : (a < b)) { tl[t] = b; tl[x] = a; }
                }
            }
            __syncthreads();
        }

    if (T >= TARGET) {
        // partition = CC of the first TARGET Kruskal-accepted edges
        for (int round = 0; round < 22; round++) {
            if (tid == 0) s_chgf = 0;
            __syncthreads();
            bool chg = false;
            for (int e = tid; e < TARGET; e += 1024) {
                unsigned idx = (unsigned)(tl[e] & 0x3FFFFFu);
                int u = idx >> 11, v = idx & (NN - 1);
                int a = lab2[u], b = lab2[v];
                int m = min(a, b);
                if (a != m) { atomicMin(&lab2[u], m); chg = true; }
                if (b != m) { atomicMin(&lab2[v], m); chg = true; }
            }
            if (chg) s_chgf = 1;
            __syncthreads();
            for (int t = tid; t < NN; t += 1024) lab2[t] = lab2[lab2[t]];
            __syncthreads();
            if (!s_chgf) break;
        }
    } else {
        // fallback (never expected): serial Kruskal tail incl. zero-jaccard pairs
        if (tid == 0) {
            int merged = 0;
            for (int e = 0; e < T && merged < TARGET; e++) {
                unsigned idx = (unsigned)(tl[e] & 0x3FFFFFu);
                int u = idx >> 11, v = idx & (NN - 1);
                int ru = ser_find(lab2, u), rv = ser_find(lab2, v);
                if (ru != rv) { lab2[rv] = ru; merged++; }
            }
            for (int i = 0; i < NN - 1 && merged < TARGET; i++)
                for (int j = i + 1; j < NN && merged < TARGET; j++)
                    if (g_inter[i * NN + j] == 0) {
                        int ri = ser_find(lab2, i), rj = ser_find(lab2, j);
                        if (ri != rj) { lab2[rj] = ri; merged++; }
                    }
            for (int v = 0; v < NN; v++) g_rminfb[v] = NN;
            for (int v = 0; v < NN; v++) {
                int r = ser_find(lab2, v);
                if (v < g_rminfb[r]) g_rminfb[r] = v;
            }
            for (int v = 0; v < NN; v++) g_labels[v] = g_rminfb[ser_find(lab2, v)];
        }
        __syncthreads();
        for (int t = tid; t < NN; t += 1024) lab2[t] = g_labels[t];
        __syncthreads();
    }

    // component minima -> sorted -> rank == first-occurrence label
    for (int v = tid; v < NN; v += 1024)
        if (lab2[v] == v) mlist[atomicAdd(&s_cnt, 1)] = v;
    __syncthreads();
    for (int k = 2; k <= MSUP; k <<= 1)
        for (int j = k >> 1; j > 0; j >>= 1) {
            for (int t = tid; t < MSUP; t += 1024) {
                int x = t ^ j;
                if (x > t) {
                    int a = mlist[t], b = mlist[x];
                    if (((t & k) == 0) ? (a > b) : (a < b)) { mlist[t] = b; mlist[x] = a; }
                }
            }
            __syncthreads();
        }
    for (int v = tid; v < NN; v += 1024) {
        int m = lab2[v];
        int lo = 0, hi = MSUP - 1;
        while (lo < hi) { int mid = (lo + hi) >> 1; if (mlist[mid] < m) lo = mid + 1; else hi = mid; }
        g_labels[v] = lo;
        atomicAdd(&ssz[lo], 1);
    }
    __syncthreads();
    for (int t = tid; t < MSUP; t += 1024)
        swc[t] = 1.0f / sqrtf((float)ssz[t] + 1e-10f);
    __syncthreads();
    for (int v = tid; v < NN; v += 1024)
        g_wnode[v] = swc[g_labels[v]];

    // member CSR (for X_coarse gather): inclusive scan of ssz (reuse mlist)
    if (tid < MSUP) mlist[tid] = ssz[tid];
    __syncthreads();
    for (int d = 1; d < MSUP; d <<= 1) {
        int v = 0;
        if (tid < MSUP && tid >= d) v = mlist[tid - d];
        __syncthreads();
        if (tid < MSUP) mlist[tid] += v;
        __syncthreads();
    }
    if (tid < MSUP) {
        int excl = mlist[tid] - ssz[tid];
        g_mstart[tid] = excl;
        cur[tid] = excl;
        g_wc[tid] = swc[tid];
    }
    if (tid == 0) g_mstart[MSUP] = NN;
    __syncthreads();
    for (int v = tid; v < NN; v += 1024) {
        int p = atomicAdd(&cur[g_labels[v]], 1);
        g_mrows[p] = v;
    }
}

// ==================== 6) fused epilogue ====================
__global__ __launch_bounds__(1024)
void k_epi(const float* __restrict__ X, float* __restrict__ out) {
    __shared__ int slabels[NN];
    __shared__ float swn[NN];
    int tid = threadIdx.x;
    int gtid = blockIdx.x * 1024 + tid;
    int nall = gridDim.x * 1024;
    for (int t = tid; t < NN; t += 1024) {
        slabels[t] = g_labels[t];
        swn[t] = g_wnode[t];
    }
    __syncthreads();
    // P
    for (int i = gtid; i < NN; i += nall)
        out[P_OFF + i * MSUP + slabels[i]] = swn[i];
    // X_coarse = P^T X : deterministic member-CSR gather, coalesced in d
    for (int idx = gtid; idx < MSUP * DF; idx += nall) {
        int s = idx >> 9, d = idx & (DF - 1);
        int b = g_mstart[s], e = g_mstart[s + 1];
        float acc = 0.0f;
        for (int m = b; m < e; m++)
            acc += X[g_mrows[m] * DF + d];
        out[XC_OFF + idx] = g_wc[s] * acc;
    }
    // A_coarse = P^T A P : A is binary by construction => edge value 1.0
    int lane = tid & 31, gw = gtid >> 5, nw = nall >> 5;
    for (int node = gw; node < NN; node += nw) {
        int d = min(g_deg[node], MAXDEG);
        float wi = swn[node];
        int li = slabels[node];
        for (int a = lane; a < d; a += 32) {
            int j = g_adj[node * MAXDEG + a];
            atomicAdd(&out[AC_OFF + li * MSUP + slabels[j]], wi * swn[j]);
        }
    }
}

// -------- launch --------
extern "C" void kernel_launch(void* const* d_in, const int* in_sizes, int n_in,
                              void* d_out, int out_size) {
    const float* X = (const float*)d_in[0];
    const float* A = (const float*)d_in[1];
    float* out = (float*)d_out;

    k_init<<<148, 1024>>>(A, out);
    k_tri<<<256, 256>>>();
    k_edges<<<NN - 1, 512>>>();          // + filtered sweep#1 + hook#1
    for (int r = 0; r < 10; r++)         // active rounds form a prefix
        k_round<<<296, 1024>>>();        // no-op after convergence
    k_finish<<<1, 1024>>>();
    k_epi<<<148, 1024>>>(X, out);
}